// round 13
// baseline (speedup 1.0000x reference)
#include <cuda_runtime.h>
#include <math.h>
#include <stdint.h>

// Problem constants
#define BB      8
#define NN      8192
#define DD      16
#define NPOINTS 1024
#define NSAMP   32
#define PP      (BB * NPOINTS * NSAMP)   // 262144 positions
#define R2      0.04f
#define NEWXYZ_ELEMS (BB * NPOINTS * 3)

typedef unsigned long long ull;

// ---------------- packed f32x2 helpers (sm_103a) ----------------
__device__ __forceinline__ ull pk2(float lo, float hi) {
    ull r; asm("mov.b64 %0, {%1, %2};" : "=l"(r) : "f"(lo), "f"(hi)); return r;
}
__device__ __forceinline__ void upk2(float& lo, float& hi, ull v) {
    asm("mov.b64 {%0, %1}, %2;" : "=f"(lo), "=f"(hi) : "l"(v));
}
__device__ __forceinline__ ull add2(ull a, ull b) {
    ull r; asm("add.rn.f32x2 %0, %1, %2;" : "=l"(r) : "l"(a), "l"(b)); return r;
}
__device__ __forceinline__ ull mul2(ull a, ull b) {
    ull r; asm("mul.rn.f32x2 %0, %1, %2;" : "=l"(r) : "l"(a), "l"(b)); return r;
}
__device__ __forceinline__ ull fma2(ull a, ull b, ull c) {
    ull r; asm("fma.rn.f32x2 %0, %1, %2, %3;" : "=l"(r) : "l"(a), "l"(b), "l"(c)); return r;
}
// one LDS.128 -> two aligned u64 packed operands
__device__ __forceinline__ void lds_w2(ull& a, ull& b, const float* p) {
    unsigned addr = (unsigned)__cvta_generic_to_shared(p);
    asm("ld.shared.v2.b64 {%0, %1}, [%2];" : "=l"(a), "=l"(b) : "r"(addr));
}

// ---------------- scratch (device globals: allocation-free) ----------------
__device__ float g_feat0[19 * PP];     // grouped features, channel-major [c][pos]
__device__ float g_x1[64 * PP];        // layer1 pre-BN
__device__ float g_x2[64 * PP];        // layer2 pre-BN
__device__ float g_x3[128 * PP];       // layer3 pre-BN
__device__ int   g_fps[BB * NPOINTS];
__device__ float g_psum[128 * 32];
__device__ float g_psq [128 * 32];
__device__ float g_bnA[128];
__device__ float g_bnC[128];

// ==========================================================================
// 1) Farthest point sampling — one block per batch, exact JAX semantics.
//    Packed f32x2 distance math: a-b computed as a+(-b) (IEEE-identical to
//    fsub.rn), squares/sums per-half identical to scalar rn ops.
//    Argmax ties -> smallest index. Single barrier per iteration: every warp
//    redundantly reduces the 32 per-warp (max,idx) slots (double-buffered).
// ==========================================================================
__global__ void __launch_bounds__(1024, 1)
fps_kernel(const float* __restrict__ xyz, const int* __restrict__ init_far,
           int* __restrict__ fps_idx)
{
    extern __shared__ float sm[];
    float* xs = sm;              // 8192
    float* ys = sm + 8192;       // 8192
    float* zs = sm + 16384;      // 8192
    int*   sidx  = (int*)(sm + 24576);          // 1024 staged indices
    unsigned* wbits = (unsigned*)(sidx + 1024); // [2][32] double-buffered
    unsigned* widx  = wbits + 64;               // [2][32]

    const int b = blockIdx.x;
    const int tid = threadIdx.x;
    const float* base = xyz + (size_t)b * NN * 3;

    // load xyz into SoA smem
    for (int i = tid; i < NN * 3; i += 1024) {
        float v = base[i];
        int p = i / 3, c = i - p * 3;
        if (c == 0) xs[p] = v; else if (c == 1) ys[p] = v; else zs[p] = v;
    }
    __syncthreads();

    // per-thread points packed in pairs: pair k = points tid+(2k)*1024, tid+(2k+1)*1024
    ull px2[4], py2[4], pz2[4];
    float dist[8];
#pragma unroll
    for (int k = 0; k < 4; k++) {
        int p0 = tid + (2 * k) * 1024;
        int p1 = p0 + 1024;
        px2[k] = pk2(xs[p0], xs[p1]);
        py2[k] = pk2(ys[p0], ys[p1]);
        pz2[k] = pk2(zs[p0], zs[p1]);
        dist[2 * k] = 1e10f; dist[2 * k + 1] = 1e10f;
    }

    int far = init_far[b];
    int par = 0;
    const int wrp = tid >> 5, lane = tid & 31;

    for (int it = 0; it < NPOINTS; ++it) {
        if (tid == 0) sidx[it] = far;           // record BEFORE update (scan semantics)
        const float cx = xs[far], cy = ys[far], cz = zs[far];
        const ull ncx = pk2(-cx, -cx);
        const ull ncy = pk2(-cy, -cy);
        const ull ncz = pk2(-cz, -cz);

        float best = -1.0f;
        int bidx = 0;
#pragma unroll
        for (int k = 0; k < 4; k++) {
            ull dx = add2(px2[k], ncx);   // == fsub.rn per half
            ull dy = add2(py2[k], ncy);
            ull dz = add2(pz2[k], ncz);
            ull s  = add2(add2(mul2(dx, dx), mul2(dy, dy)), mul2(dz, dz));
            float d0, d1; upk2(d0, d1, s);
            float n0 = fminf(dist[2 * k], d0);     dist[2 * k] = n0;
            float n1 = fminf(dist[2 * k + 1], d1); dist[2 * k + 1] = n1;
            if (n0 > best) { best = n0; bidx = tid + (2 * k) * 1024; }     // strict >
            if (n1 > best) { best = n1; bidx = tid + (2 * k + 1) * 1024; }
        }

        // warp argmax: dist bits are monotone (all >= 0)
        unsigned bb = __float_as_uint(best);
        unsigned wm = __reduce_max_sync(0xffffffffu, bb);
        unsigned ci = (bb == wm) ? (unsigned)bidx : 0xffffffffu;
        unsigned wi = __reduce_min_sync(0xffffffffu, ci);
        if (lane == 0) { wbits[par * 32 + wrp] = wm; widx[par * 32 + wrp] = wi; }
        __syncthreads();
        // every warp redundantly reduces the 32 slots -> no second barrier
        unsigned b2 = wbits[par * 32 + lane];
        unsigned i2 = widx [par * 32 + lane];
        unsigned m2 = __reduce_max_sync(0xffffffffu, b2);
        unsigned c2 = (b2 == m2) ? i2 : 0xffffffffu;
        far = (int)__reduce_min_sync(0xffffffffu, c2);
        par ^= 1;
    }
    __syncthreads();
    for (int i = tid; i < NPOINTS; i += 1024) fps_idx[b * NPOINTS + i] = sidx[i];
}

// ==========================================================================
// 2) Ball query + grouping — one warp per (b, s). First 32 indices (ascending)
//    with sq <= r^2; pad with the first. Writes new_xyz to d_out and grouped
//    features [3 xyz-norm + 16 points] channel-major into g_feat0.
// ==========================================================================
__global__ void __launch_bounds__(256)
ball_group_kernel(const float* __restrict__ xyz, const float* __restrict__ pts,
                  const int* __restrict__ fps_idx,
                  float* __restrict__ newxyz_out, float* __restrict__ feat0)
{
    __shared__ int buf[8][NSAMP];
    const int gw = (blockIdx.x * blockDim.x + threadIdx.x) >> 5;
    const int lane = threadIdx.x & 31;
    const int wloc = (threadIdx.x >> 5);
    if (gw >= BB * NPOINTS) return;
    const int b = gw >> 10;

    const float* xb = xyz + (size_t)b * NN * 3;
    const int cidx = fps_idx[gw];
    const float cx = xb[cidx * 3], cy = xb[cidx * 3 + 1], cz = xb[cidx * 3 + 2];
    if (lane < 3) newxyz_out[gw * 3 + lane] = xb[cidx * 3 + lane];

    const float c2 = __fadd_rn(__fadd_rn(__fmul_rn(cx, cx), __fmul_rn(cy, cy)),
                               __fmul_rn(cz, cz));
    int cnt = 0;
    for (int chunk = 0; chunk < NN / 32 && cnt < NSAMP; ++chunk) {
        const int p = chunk * 32 + lane;
        const float x = xb[p * 3], y = xb[p * 3 + 1], z = xb[p * 3 + 2];
        const float dot = fmaf(z, cz, fmaf(y, cy, __fmul_rn(x, cx)));
        const float p2  = __fadd_rn(__fadd_rn(__fmul_rn(x, x), __fmul_rn(y, y)),
                                    __fmul_rn(z, z));
        const float sq  = __fadd_rn(__fadd_rn(__fmul_rn(-2.0f, dot), c2), p2);
        const bool pred = !(sq > R2);
        const unsigned m = __ballot_sync(0xffffffffu, pred);
        if (pred) {
            const int pos = cnt + __popc(m & ((1u << lane) - 1u));
            if (pos < NSAMP) buf[wloc][pos] = p;
        }
        cnt += __popc(m);
    }
    __syncwarp();
    if (cnt < NSAMP) {
        const int first = buf[wloc][0];   // cnt >= 1 always (center itself qualifies)
        if (lane >= cnt) buf[wloc][lane] = first;
    }
    __syncwarp();

    // gather: lane k handles sample k
    const int gi = buf[wloc][lane];
    const float* gp = xb + gi * 3;
    const size_t posn = (size_t)gw * NSAMP + lane;
    feat0[0 * (size_t)PP + posn] = __fsub_rn(gp[0], cx);
    feat0[1 * (size_t)PP + posn] = __fsub_rn(gp[1], cy);
    feat0[2 * (size_t)PP + posn] = __fsub_rn(gp[2], cz);
    const float* pr = pts + ((size_t)b * NN + gi) * DD;
#pragma unroll
    for (int c = 0; c < DD; c++)
        feat0[(size_t)(3 + c) * PP + posn] = pr[c];
}

// ==========================================================================
// 3) Pointwise conv (CIN -> 64), optional fused BN+ReLU on the input.
//    1 thread = 1 position; 32 PACKED f32x2 accumulators (pairs of output
//    channels) -> FFMA2 halves fma-pipe instruction count. Weights read from
//    smem via ld.shared.v2.b64 (one LDS.128 -> two aligned u64 operands).
//    Per-channel fma chain order identical to the scalar version.
// ==========================================================================
template <int CIN, bool HASBN>
__global__ void __launch_bounds__(256)
conv64_kernel(const float* __restrict__ in, const float* __restrict__ w,
              const float* __restrict__ bias,
              const float* __restrict__ bnA, const float* __restrict__ bnC,
              float* __restrict__ out)
{
    __shared__ __align__(16) float ws[CIN * 64];   // [c][o]
    __shared__ float sA[CIN], sC[CIN], sB[64];
    const int tid = threadIdx.x;
    for (int i = tid; i < CIN * 64; i += 256) {
        int o = i / CIN, c = i - o * CIN;
        ws[c * 64 + o] = w[i];
    }
    if (tid < 64) sB[tid] = bias[tid];
    if (HASBN) for (int i = tid; i < CIN; i += 256) { sA[i] = bnA[i]; sC[i] = bnC[i]; }
    __syncthreads();

    const int pos = blockIdx.x * 256 + tid;
    ull acc[32];
#pragma unroll
    for (int j = 0; j < 32; j++) acc[j] = pk2(sB[2 * j], sB[2 * j + 1]);

#pragma unroll 4
    for (int c = 0; c < CIN; c++) {
        float v = in[(size_t)c * PP + pos];
        if (HASBN) v = fmaxf(fmaf(v, sA[c], sC[c]), 0.0f);
        const ull vv = pk2(v, v);
        const float* wr = ws + c * 64;
#pragma unroll
        for (int j = 0; j < 16; j++) {
            ull w01, w23;
            lds_w2(w01, w23, wr + 4 * j);          // LDS.128 broadcast
            acc[2 * j]     = fma2(w01, vv, acc[2 * j]);
            acc[2 * j + 1] = fma2(w23, vv, acc[2 * j + 1]);
        }
    }
#pragma unroll
    for (int j = 0; j < 32; j++) {
        float a0, a1; upk2(a0, a1, acc[j]);
        out[(size_t)(2 * j)     * PP + pos] = a0;
        out[(size_t)(2 * j + 1) * PP + pos] = a1;
    }
}

// ==========================================================================
// 4) Deterministic per-channel stats (sum, sumsq): grid (C, 32 slices)
// ==========================================================================
__global__ void __launch_bounds__(256)
stats_kernel(const float* __restrict__ x, float* __restrict__ psum,
             float* __restrict__ psq)
{
    const int c = blockIdx.x, sl = blockIdx.y;
    const float* p = x + (size_t)c * PP + (size_t)sl * 8192;
    float s = 0.f, q = 0.f;
    for (int i = threadIdx.x; i < 8192; i += 256) {
        float v = p[i];
        s += v; q += v * v;
    }
    __shared__ float rs[256], rq[256];
    rs[threadIdx.x] = s; rq[threadIdx.x] = q;
    __syncthreads();
    for (int st = 128; st > 0; st >>= 1) {
        if (threadIdx.x < st) {
            rs[threadIdx.x] += rs[threadIdx.x + st];
            rq[threadIdx.x] += rq[threadIdx.x + st];
        }
        __syncthreads();
    }
    if (threadIdx.x == 0) { psum[c * 32 + sl] = rs[0]; psq[c * 32 + sl] = rq[0]; }
}

__global__ void bn_finalize_kernel(const float* __restrict__ psum,
                                   const float* __restrict__ psq,
                                   const float* __restrict__ g,
                                   const float* __restrict__ be,
                                   float* __restrict__ A, float* __restrict__ C,
                                   int nC)
{
    const int c = blockIdx.x * blockDim.x + threadIdx.x;
    if (c >= nC) return;
    double s = 0.0, q = 0.0;
    for (int i = 0; i < 32; i++) { s += (double)psum[c * 32 + i]; q += (double)psq[c * 32 + i]; }
    const double mean = s / (double)PP;
    const double var  = q / (double)PP - mean * mean;
    const double inv  = 1.0 / sqrt(var + 1e-5);
    const double a    = (double)g[c] * inv;
    A[c] = (float)a;
    C[c] = (float)((double)be[c] - mean * a);
}

// ==========================================================================
// 5) BN + ReLU + max over the 32 samples; writes (B, S, 128) part of d_out.
// ==========================================================================
__global__ void __launch_bounds__(256)
maxpool_kernel(const float* __restrict__ x, const float* __restrict__ A,
               const float* __restrict__ C, float* __restrict__ out)
{
    const int idx = blockIdx.x * 256 + threadIdx.x;  // < 8*1024*128
    const int o = idx & 127, bs = idx >> 7;
    const float4* p = reinterpret_cast<const float4*>(x + (size_t)o * PP + (size_t)bs * NSAMP);
    const float a = A[o], cc = C[o];
    float m = -1e30f;
#pragma unroll
    for (int k = 0; k < 8; k++) {
        float4 v = p[k];
        m = fmaxf(m, fmaf(v.x, a, cc));
        m = fmaxf(m, fmaf(v.y, a, cc));
        m = fmaxf(m, fmaf(v.z, a, cc));
        m = fmaxf(m, fmaf(v.w, a, cc));
    }
    out[idx] = fmaxf(m, 0.0f);   // relu commutes with max
}

// ==========================================================================
// launch
// ==========================================================================
extern "C" void kernel_launch(void* const* d_in, const int* in_sizes, int n_in,
                              void* d_out, int out_size)
{
    const float* xyz      = (const float*)d_in[0];
    const float* pts      = (const float*)d_in[1];
    const int*   init_far = (const int*)  d_in[2];
    const float* w0 = (const float*)d_in[3],  *b0 = (const float*)d_in[4];
    const float* g0 = (const float*)d_in[5],  *be0 = (const float*)d_in[6];
    const float* w1 = (const float*)d_in[7],  *b1 = (const float*)d_in[8];
    const float* g1 = (const float*)d_in[9],  *be1 = (const float*)d_in[10];
    const float* w2 = (const float*)d_in[11], *b2 = (const float*)d_in[12];
    const float* g2 = (const float*)d_in[13], *be2 = (const float*)d_in[14];

    float* out = (float*)d_out;
    float* out_newxyz = out;                  // (B, 1024, 3)
    float* out_feat   = out + NEWXYZ_ELEMS;   // (B, 1024, 128)

    float *feat0, *x1, *x2, *x3, *psum, *psq, *bnA, *bnC;
    int* fpsIdx;
    cudaGetSymbolAddress((void**)&feat0,  g_feat0);
    cudaGetSymbolAddress((void**)&x1,     g_x1);
    cudaGetSymbolAddress((void**)&x2,     g_x2);
    cudaGetSymbolAddress((void**)&x3,     g_x3);
    cudaGetSymbolAddress((void**)&psum,   g_psum);
    cudaGetSymbolAddress((void**)&psq,    g_psq);
    cudaGetSymbolAddress((void**)&bnA,    g_bnA);
    cudaGetSymbolAddress((void**)&bnC,    g_bnC);
    cudaGetSymbolAddress((void**)&fpsIdx, g_fps);

    const int fps_smem = (NN * 3 + NPOINTS) * 4 + 64 * 4 * 2 + 16;
    cudaFuncSetAttribute(fps_kernel, cudaFuncAttributeMaxDynamicSharedMemorySize, fps_smem);

    // 1) FPS
    fps_kernel<<<BB, 1024, fps_smem>>>(xyz, init_far, fpsIdx);
    // 2) ball query + grouping (+ writes new_xyz)
    ball_group_kernel<<<(BB * NPOINTS) / 8, 256>>>(xyz, pts, fpsIdx, out_newxyz, feat0);
    // 3) layer 1: 19 -> 64
    conv64_kernel<19, false><<<PP / 256, 256>>>(feat0, w0, b0, nullptr, nullptr, x1);
    stats_kernel<<<dim3(64, 32), 256>>>(x1, psum, psq);
    bn_finalize_kernel<<<1, 64>>>(psum, psq, g0, be0, bnA, bnC, 64);
    // 4) layer 2: 64 -> 64 (BN1+ReLU fused on input)
    conv64_kernel<64, true><<<PP / 256, 256>>>(x1, w1, b1, bnA, bnC, x2);
    stats_kernel<<<dim3(64, 32), 256>>>(x2, psum, psq);
    bn_finalize_kernel<<<1, 64>>>(psum, psq, g1, be1, bnA, bnC, 64);
    // 5) layer 3: 64 -> 128 (two 64-out halves, BN2+ReLU fused on input)
    conv64_kernel<64, true><<<PP / 256, 256>>>(x2, w2,           b2,      bnA, bnC, x3);
    conv64_kernel<64, true><<<PP / 256, 256>>>(x2, w2 + 64 * 64, b2 + 64, bnA, bnC,
                                               x3 + (size_t)64 * PP);
    stats_kernel<<<dim3(128, 32), 256>>>(x3, psum, psq);
    bn_finalize_kernel<<<1, 128>>>(psum, psq, g2, be2, bnA, bnC, 128);
    // 6) BN3 + ReLU + max over samples
    maxpool_kernel<<<(BB * NPOINTS * 128) / 256, 256>>>(x3, bnA, bnC, out_feat);
}

// round 14
// speedup vs baseline: 1.1288x; 1.1288x over previous
#include <cuda_runtime.h>
#include <math.h>
#include <stdint.h>

// Problem constants
#define BB      8
#define NN      8192
#define DD      16
#define NPOINTS 1024
#define NSAMP   32
#define PP      (BB * NPOINTS * NSAMP)   // 262144 positions
#define R2      0.04f
#define NEWXYZ_ELEMS (BB * NPOINTS * 3)

typedef unsigned long long ull;

// ---------------- packed f32x2 helpers (sm_103a) ----------------
__device__ __forceinline__ ull pk2(float lo, float hi) {
    ull r; asm("mov.b64 %0, {%1, %2};" : "=l"(r) : "f"(lo), "f"(hi)); return r;
}
__device__ __forceinline__ void upk2(float& lo, float& hi, ull v) {
    asm("mov.b64 {%0, %1}, %2;" : "=f"(lo), "=f"(hi) : "l"(v));
}
__device__ __forceinline__ ull add2(ull a, ull b) {
    ull r; asm("add.rn.f32x2 %0, %1, %2;" : "=l"(r) : "l"(a), "l"(b)); return r;
}
__device__ __forceinline__ ull mul2(ull a, ull b) {
    ull r; asm("mul.rn.f32x2 %0, %1, %2;" : "=l"(r) : "l"(a), "l"(b)); return r;
}
__device__ __forceinline__ ull fma2(ull a, ull b, ull c) {
    ull r; asm("fma.rn.f32x2 %0, %1, %2, %3;" : "=l"(r) : "l"(a), "l"(b), "l"(c)); return r;
}
// one LDS.128 -> two aligned u64 packed operands
__device__ __forceinline__ void lds_w2(ull& a, ull& b, const float* p) {
    unsigned addr = (unsigned)__cvta_generic_to_shared(p);
    asm("ld.shared.v2.b64 {%0, %1}, [%2];" : "=l"(a), "=l"(b) : "r"(addr));
}

__device__ __forceinline__ int mor3(int v) {            // spread 3 bits
    return (v & 1) | ((v & 2) << 2) | ((v & 4) << 4);
}

// ---------------- scratch (device globals: allocation-free) ----------------
__device__ float g_feat0[19 * PP];     // grouped features, channel-major [c][pos]
__device__ float g_x1[64 * PP];        // layer1 pre-BN
__device__ float g_x2[64 * PP];        // layer2 pre-BN
__device__ float g_x3[128 * PP];       // layer3 pre-BN
__device__ int   g_fps[BB * NPOINTS];
__device__ float g_psum[128 * 32];
__device__ float g_psq [128 * 32];
__device__ float g_bnA[128];
__device__ float g_bnC[128];

// ==========================================================================
// 1) Farthest point sampling — one block per batch, exact JAX semantics,
//    with EXACT warp-level spatial pruning:
//      * points Morton-binned once; warp w owns binned slots [512w, 512w+512)
//      * per-thread 16 points SORTED by original index (strict-> scan ==
//        min-orig-index tie-break, matching jnp.argmax)
//      * per iteration, warp skips its update iff
//          boxdist^2(centroid, warp bbox) * 0.999 >= warp max dist
//        which guarantees d(p,c) >= dist[p] for every owned point, so the
//        stored dists / warp max / warp argmax remain bitwise valid.
//    Atomic scatter makes the PARTITION nondeterministic, but max / min-index
//    reductions over the full point set are partition-independent, so the
//    selected index sequence (and all outputs) are bitwise deterministic.
// ==========================================================================
__global__ void __launch_bounds__(512, 1)
fps_kernel(const float* __restrict__ xyz, const int* __restrict__ init_far,
           int* __restrict__ fps_idx)
{
    extern __shared__ float sm[];
    float* xs = sm;                       // 8192 (binned after setup)
    float* ys = xs + 8192;
    float* zs = ys + 8192;
    int*   sidx = (int*)(zs + 8192);      // 1024 staged output indices
    unsigned* wbits = (unsigned*)(sidx + 1024); // [2][16] double-buffered
    unsigned* widx  = wbits + 32;               // [2][16]
    unsigned* cnt   = widx + 32;          // 512 cell counts
    unsigned* sptr  = cnt + 512;          // 512 scatter pointers
    unsigned* wsum  = sptr + 512;         // 16 warp partial sums
    unsigned short* posof = (unsigned short*)(wsum + 16);  // 8192: orig -> binpos
    unsigned short* oidx  = posof + 8192;                  // 8192: binpos -> orig

    const int b    = blockIdx.x;
    const int tid  = threadIdx.x;         // 0..511
    const int lane = tid & 31, wrp = tid >> 5;
    const float* base = xyz + (size_t)b * NN * 3;

    // ---- load xyz into SoA smem (orig order) ----
    for (int i = tid; i < NN * 3; i += 512) {
        float v = base[i];
        int p = i / 3, c = i - p * 3;
        if (c == 0) xs[p] = v; else if (c == 1) ys[p] = v; else zs[p] = v;
    }
    cnt[tid] = 0;
    __syncthreads();

    // ---- read 16 orig points to regs, histogram Morton cells ----
    float x[16], y[16], z[16];
    unsigned o[16];
#pragma unroll
    for (int j = 0; j < 16; j++) {
        int p = tid + j * 512;
        x[j] = xs[p]; y[j] = ys[p]; z[j] = zs[p]; o[j] = (unsigned)p;
        int cx = min(7, (int)(x[j] * 8.0f));
        int cy = min(7, (int)(y[j] * 8.0f));
        int cz = min(7, (int)(z[j] * 8.0f));
        atomicAdd(&cnt[mor3(cx) | (mor3(cy) << 1) | (mor3(cz) << 2)], 1u);
    }
    __syncthreads();

    // ---- exclusive scan of cnt[512] -> sptr ----
    {
        unsigned c0 = cnt[tid], ci = c0;
#pragma unroll
        for (int off = 1; off < 32; off <<= 1) {
            unsigned n = __shfl_up_sync(0xffffffffu, ci, off);
            if (lane >= off) ci += n;
        }
        if (lane == 31) wsum[wrp] = ci;
        __syncthreads();
        unsigned woff = 0;
        for (int w = 0; w < wrp; w++) woff += wsum[w];
        sptr[tid] = woff + ci - c0;
    }
    __syncthreads();

    // ---- scatter into binned order (overwrites xs/ys/zs; coords in regs) ----
#pragma unroll
    for (int j = 0; j < 16; j++) {
        int cx = min(7, (int)(x[j] * 8.0f));
        int cy = min(7, (int)(y[j] * 8.0f));
        int cz = min(7, (int)(z[j] * 8.0f));
        int cell = mor3(cx) | (mor3(cy) << 1) | (mor3(cz) << 2);
        unsigned pos = atomicAdd(&sptr[cell], 1u);
        xs[pos] = x[j]; ys[pos] = y[j]; zs[pos] = z[j];
        oidx[pos]  = (unsigned short)o[j];
        posof[o[j]] = (unsigned short)pos;
    }
    __syncthreads();

    // ---- re-read this warp's 512-slot region: thread takes lane + 32j ----
#pragma unroll
    for (int j = 0; j < 16; j++) {
        int p = wrp * 512 + lane + j * 32;
        x[j] = xs[p]; y[j] = ys[p]; z[j] = zs[p];
        o[j] = (unsigned)oidx[p];
    }

    // ---- sort 16 tuples by orig index ascending (static exchange network) ----
#pragma unroll
    for (int a = 0; a < 15; a++)
#pragma unroll
        for (int bq = a + 1; bq < 16; bq++)
            if (o[bq] < o[a]) {
                unsigned to = o[a]; o[a] = o[bq]; o[bq] = to;
                float t;
                t = x[a]; x[a] = x[bq]; x[bq] = t;
                t = y[a]; y[a] = y[bq]; y[bq] = t;
                t = z[a]; z[a] = z[bq]; z[bq] = t;
            }

    // ---- warp bbox over its 512 points (coords >= 0: bits monotone) ----
    float xl = x[0], xh = x[0], yl = y[0], yh = y[0], zl = z[0], zh = z[0];
#pragma unroll
    for (int j = 1; j < 16; j++) {
        xl = fminf(xl, x[j]); xh = fmaxf(xh, x[j]);
        yl = fminf(yl, y[j]); yh = fmaxf(yh, y[j]);
        zl = fminf(zl, z[j]); zh = fmaxf(zh, z[j]);
    }
    xl = __uint_as_float(__reduce_min_sync(0xffffffffu, __float_as_uint(xl)));
    xh = __uint_as_float(__reduce_max_sync(0xffffffffu, __float_as_uint(xh)));
    yl = __uint_as_float(__reduce_min_sync(0xffffffffu, __float_as_uint(yl)));
    yh = __uint_as_float(__reduce_max_sync(0xffffffffu, __float_as_uint(yh)));
    zl = __uint_as_float(__reduce_min_sync(0xffffffffu, __float_as_uint(zl)));
    zh = __uint_as_float(__reduce_max_sync(0xffffffffu, __float_as_uint(zh)));

    // ---- pack coordinate pairs (scan order j=0..15 == ascending orig) ----
    ull px2[8], py2[8], pz2[8];
    float dist[16];
#pragma unroll
    for (int k = 0; k < 8; k++) {
        px2[k] = pk2(x[2 * k], x[2 * k + 1]);
        py2[k] = pk2(y[2 * k], y[2 * k + 1]);
        pz2[k] = pk2(z[2 * k], z[2 * k + 1]);
        dist[2 * k] = 1e10f; dist[2 * k + 1] = 1e10f;
    }

    unsigned wm = __float_as_uint(1e10f);   // warp max dist (persistent)
    unsigned wi = 0;                        // its min orig index (persistent)
    int far = init_far[b];
    int par = 0;

    for (int it = 0; it < NPOINTS; ++it) {
        if (tid == 0) sidx[it] = far;       // record BEFORE update (scan semantics)
        const int binp = (int)posof[far];   // centroid position in binned arrays
        const float cx = xs[binp], cy = ys[binp], cz = zs[binp];

        // exact warp-level prune: skip iff boxdist^2*0.999 >= warp max dist
        float gx = fmaxf(fmaxf(xl - cx, cx - xh), 0.0f);
        float gy = fmaxf(fmaxf(yl - cy, cy - yh), 0.0f);
        float gz = fmaxf(fmaxf(zl - cz, cz - zh), 0.0f);
        float lb = (gx * gx + gy * gy + gz * gz) * 0.999f;

        if (lb < __uint_as_float(wm)) {     // ACTIVE: do the real update
            const ull ncx = pk2(-cx, -cx);
            const ull ncy = pk2(-cy, -cy);
            const ull ncz = pk2(-cz, -cz);
            float best = -1.0f; unsigned borig = 0;
#pragma unroll
            for (int k = 0; k < 8; k++) {
                ull dx = add2(px2[k], ncx);   // == fsub.rn per half
                ull dy = add2(py2[k], ncy);
                ull dz = add2(pz2[k], ncz);
                ull s  = add2(add2(mul2(dx, dx), mul2(dy, dy)), mul2(dz, dz));
                float d0, d1; upk2(d0, d1, s);
                float n0 = fminf(dist[2 * k], d0);     dist[2 * k] = n0;
                float n1 = fminf(dist[2 * k + 1], d1); dist[2 * k + 1] = n1;
                if (n0 > best) { best = n0; borig = o[2 * k]; }     // strict >
                if (n1 > best) { best = n1; borig = o[2 * k + 1]; } // == first max
            }
            unsigned bb = __float_as_uint(best);
            wm = __reduce_max_sync(0xffffffffu, bb);
            unsigned ci = (bb == wm) ? borig : 0xffffffffu;
            wi = __reduce_min_sync(0xffffffffu, ci);
        }
        if (lane == 0) { wbits[par * 16 + wrp] = wm; widx[par * 16 + wrp] = wi; }
        __syncthreads();
        // every warp redundantly reduces the 16 slots -> single barrier/iter
        unsigned b2 = (lane < 16) ? wbits[par * 16 + lane] : 0u;
        unsigned i2 = (lane < 16) ? widx [par * 16 + lane] : 0xffffffffu;
        unsigned m2 = __reduce_max_sync(0xffffffffu, b2);
        unsigned c2 = (b2 == m2) ? i2 : 0xffffffffu;
        far = (int)__reduce_min_sync(0xffffffffu, c2);
        par ^= 1;
    }
    __syncthreads();
    for (int i = tid; i < NPOINTS; i += 512) fps_idx[b * NPOINTS + i] = sidx[i];
}

// ==========================================================================
// 2) Ball query + grouping — one warp per (b, s). First 32 indices (ascending)
//    with sq <= r^2; pad with the first. Writes new_xyz to d_out and grouped
//    features [3 xyz-norm + 16 points] channel-major into g_feat0.
// ==========================================================================
__global__ void __launch_bounds__(256)
ball_group_kernel(const float* __restrict__ xyz, const float* __restrict__ pts,
                  const int* __restrict__ fps_idx,
                  float* __restrict__ newxyz_out, float* __restrict__ feat0)
{
    __shared__ int buf[8][NSAMP];
    const int gw = (blockIdx.x * blockDim.x + threadIdx.x) >> 5;
    const int lane = threadIdx.x & 31;
    const int wloc = (threadIdx.x >> 5);
    if (gw >= BB * NPOINTS) return;
    const int b = gw >> 10;

    const float* xb = xyz + (size_t)b * NN * 3;
    const int cidx = fps_idx[gw];
    const float cx = xb[cidx * 3], cy = xb[cidx * 3 + 1], cz = xb[cidx * 3 + 2];
    if (lane < 3) newxyz_out[gw * 3 + lane] = xb[cidx * 3 + lane];

    const float c2 = __fadd_rn(__fadd_rn(__fmul_rn(cx, cx), __fmul_rn(cy, cy)),
                               __fmul_rn(cz, cz));
    int cnt = 0;
    for (int chunk = 0; chunk < NN / 32 && cnt < NSAMP; ++chunk) {
        const int p = chunk * 32 + lane;
        const float x = xb[p * 3], y = xb[p * 3 + 1], z = xb[p * 3 + 2];
        const float dot = fmaf(z, cz, fmaf(y, cy, __fmul_rn(x, cx)));
        const float p2  = __fadd_rn(__fadd_rn(__fmul_rn(x, x), __fmul_rn(y, y)),
                                    __fmul_rn(z, z));
        const float sq  = __fadd_rn(__fadd_rn(__fmul_rn(-2.0f, dot), c2), p2);
        const bool pred = !(sq > R2);
        const unsigned m = __ballot_sync(0xffffffffu, pred);
        if (pred) {
            const int pos = cnt + __popc(m & ((1u << lane) - 1u));
            if (pos < NSAMP) buf[wloc][pos] = p;
        }
        cnt += __popc(m);
    }
    __syncwarp();
    if (cnt < NSAMP) {
        const int first = buf[wloc][0];   // cnt >= 1 always (center itself qualifies)
        if (lane >= cnt) buf[wloc][lane] = first;
    }
    __syncwarp();

    // gather: lane k handles sample k
    const int gi = buf[wloc][lane];
    const float* gp = xb + gi * 3;
    const size_t posn = (size_t)gw * NSAMP + lane;
    feat0[0 * (size_t)PP + posn] = __fsub_rn(gp[0], cx);
    feat0[1 * (size_t)PP + posn] = __fsub_rn(gp[1], cy);
    feat0[2 * (size_t)PP + posn] = __fsub_rn(gp[2], cz);
    const float* pr = pts + ((size_t)b * NN + gi) * DD;
#pragma unroll
    for (int c = 0; c < DD; c++)
        feat0[(size_t)(3 + c) * PP + posn] = pr[c];
}

// ==========================================================================
// 3) Pointwise conv (CIN -> 64), optional fused BN+ReLU on the input.
//    1 thread = 1 position; 32 PACKED f32x2 accumulators (pairs of output
//    channels). Weights read via ld.shared.v2.b64 (one LDS.128 broadcast).
// ==========================================================================
template <int CIN, bool HASBN>
__global__ void __launch_bounds__(256)
conv64_kernel(const float* __restrict__ in, const float* __restrict__ w,
              const float* __restrict__ bias,
              const float* __restrict__ bnA, const float* __restrict__ bnC,
              float* __restrict__ out)
{
    __shared__ __align__(16) float ws[CIN * 64];   // [c][o]
    __shared__ float sA[CIN], sC[CIN], sB[64];
    const int tid = threadIdx.x;
    for (int i = tid; i < CIN * 64; i += 256) {
        int o = i / CIN, c = i - o * CIN;
        ws[c * 64 + o] = w[i];
    }
    if (tid < 64) sB[tid] = bias[tid];
    if (HASBN) for (int i = tid; i < CIN; i += 256) { sA[i] = bnA[i]; sC[i] = bnC[i]; }
    __syncthreads();

    const int pos = blockIdx.x * 256 + tid;
    ull acc[32];
#pragma unroll
    for (int j = 0; j < 32; j++) acc[j] = pk2(sB[2 * j], sB[2 * j + 1]);

#pragma unroll 4
    for (int c = 0; c < CIN; c++) {
        float v = in[(size_t)c * PP + pos];
        if (HASBN) v = fmaxf(fmaf(v, sA[c], sC[c]), 0.0f);
        const ull vv = pk2(v, v);
        const float* wr = ws + c * 64;
#pragma unroll
        for (int j = 0; j < 16; j++) {
            ull w01, w23;
            lds_w2(w01, w23, wr + 4 * j);          // LDS.128 broadcast
            acc[2 * j]     = fma2(w01, vv, acc[2 * j]);
            acc[2 * j + 1] = fma2(w23, vv, acc[2 * j + 1]);
        }
    }
#pragma unroll
    for (int j = 0; j < 32; j++) {
        float a0, a1; upk2(a0, a1, acc[j]);
        out[(size_t)(2 * j)     * PP + pos] = a0;
        out[(size_t)(2 * j + 1) * PP + pos] = a1;
    }
}

// ==========================================================================
// 4) Deterministic per-channel stats (sum, sumsq): grid (C, 32 slices).
//    float4 loads for DRAM efficiency.
// ==========================================================================
__global__ void __launch_bounds__(256)
stats_kernel(const float* __restrict__ x, float* __restrict__ psum,
             float* __restrict__ psq)
{
    const int c = blockIdx.x, sl = blockIdx.y;
    const float4* p = reinterpret_cast<const float4*>(
        x + (size_t)c * PP + (size_t)sl * 8192);
    float s = 0.f, q = 0.f;
    for (int i = threadIdx.x; i < 2048; i += 256) {
        float4 v = p[i];
        s += v.x; q += v.x * v.x;
        s += v.y; q += v.y * v.y;
        s += v.z; q += v.z * v.z;
        s += v.w; q += v.w * v.w;
    }
    __shared__ float rs[256], rq[256];
    rs[threadIdx.x] = s; rq[threadIdx.x] = q;
    __syncthreads();
    for (int st = 128; st > 0; st >>= 1) {
        if (threadIdx.x < st) {
            rs[threadIdx.x] += rs[threadIdx.x + st];
            rq[threadIdx.x] += rq[threadIdx.x + st];
        }
        __syncthreads();
    }
    if (threadIdx.x == 0) { psum[c * 32 + sl] = rs[0]; psq[c * 32 + sl] = rq[0]; }
}

__global__ void bn_finalize_kernel(const float* __restrict__ psum,
                                   const float* __restrict__ psq,
                                   const float* __restrict__ g,
                                   const float* __restrict__ be,
                                   float* __restrict__ A, float* __restrict__ C,
                                   int nC)
{
    const int c = blockIdx.x * blockDim.x + threadIdx.x;
    if (c >= nC) return;
    double s = 0.0, q = 0.0;
    for (int i = 0; i < 32; i++) { s += (double)psum[c * 32 + i]; q += (double)psq[c * 32 + i]; }
    const double mean = s / (double)PP;
    const double var  = q / (double)PP - mean * mean;
    const double inv  = 1.0 / sqrt(var + 1e-5);
    const double a    = (double)g[c] * inv;
    A[c] = (float)a;
    C[c] = (float)((double)be[c] - mean * a);
}

// ==========================================================================
// 5) BN + ReLU + max over the 32 samples; writes (B, S, 128) part of d_out.
// ==========================================================================
__global__ void __launch_bounds__(256)
maxpool_kernel(const float* __restrict__ x, const float* __restrict__ A,
               const float* __restrict__ C, float* __restrict__ out)
{
    const int idx = blockIdx.x * 256 + threadIdx.x;  // < 8*1024*128
    const int o = idx & 127, bs = idx >> 7;
    const float4* p = reinterpret_cast<const float4*>(x + (size_t)o * PP + (size_t)bs * NSAMP);
    const float a = A[o], cc = C[o];
    float m = -1e30f;
#pragma unroll
    for (int k = 0; k < 8; k++) {
        float4 v = p[k];
        m = fmaxf(m, fmaf(v.x, a, cc));
        m = fmaxf(m, fmaf(v.y, a, cc));
        m = fmaxf(m, fmaf(v.z, a, cc));
        m = fmaxf(m, fmaf(v.w, a, cc));
    }
    out[idx] = fmaxf(m, 0.0f);   // relu commutes with max
}

// ==========================================================================
// launch
// ==========================================================================
extern "C" void kernel_launch(void* const* d_in, const int* in_sizes, int n_in,
                              void* d_out, int out_size)
{
    const float* xyz      = (const float*)d_in[0];
    const float* pts      = (const float*)d_in[1];
    const int*   init_far = (const int*)  d_in[2];
    const float* w0 = (const float*)d_in[3],  *b0 = (const float*)d_in[4];
    const float* g0 = (const float*)d_in[5],  *be0 = (const float*)d_in[6];
    const float* w1 = (const float*)d_in[7],  *b1 = (const float*)d_in[8];
    const float* g1 = (const float*)d_in[9],  *be1 = (const float*)d_in[10];
    const float* w2 = (const float*)d_in[11], *b2 = (const float*)d_in[12];
    const float* g2 = (const float*)d_in[13], *be2 = (const float*)d_in[14];

    float* out = (float*)d_out;
    float* out_newxyz = out;                  // (B, 1024, 3)
    float* out_feat   = out + NEWXYZ_ELEMS;   // (B, 1024, 128)

    float *feat0, *x1, *x2, *x3, *psum, *psq, *bnA, *bnC;
    int* fpsIdx;
    cudaGetSymbolAddress((void**)&feat0,  g_feat0);
    cudaGetSymbolAddress((void**)&x1,     g_x1);
    cudaGetSymbolAddress((void**)&x2,     g_x2);
    cudaGetSymbolAddress((void**)&x3,     g_x3);
    cudaGetSymbolAddress((void**)&psum,   g_psum);
    cudaGetSymbolAddress((void**)&psq,    g_psq);
    cudaGetSymbolAddress((void**)&bnA,    g_bnA);
    cudaGetSymbolAddress((void**)&bnC,    g_bnC);
    cudaGetSymbolAddress((void**)&fpsIdx, g_fps);

    // smem: xs/ys/zs(3*8192) + sidx(1024) + slots(64) + cnt(512)+sptr(512)+wsum(16)
    //       floats, + 2 * 8192 u16
    const int fps_smem = (3 * 8192 + 1024 + 64 + 512 + 512 + 16) * 4
                       + 2 * 8192 * 2 + 256;
    cudaFuncSetAttribute(fps_kernel, cudaFuncAttributeMaxDynamicSharedMemorySize, fps_smem);

    // 1) FPS (spatially-pruned, exact)
    fps_kernel<<<BB, 512, fps_smem>>>(xyz, init_far, fpsIdx);
    // 2) ball query + grouping (+ writes new_xyz)
    ball_group_kernel<<<(BB * NPOINTS) / 8, 256>>>(xyz, pts, fpsIdx, out_newxyz, feat0);
    // 3) layer 1: 19 -> 64
    conv64_kernel<19, false><<<PP / 256, 256>>>(feat0, w0, b0, nullptr, nullptr, x1);
    stats_kernel<<<dim3(64, 32), 256>>>(x1, psum, psq);
    bn_finalize_kernel<<<1, 64>>>(psum, psq, g0, be0, bnA, bnC, 64);
    // 4) layer 2: 64 -> 64 (BN1+ReLU fused on input)
    conv64_kernel<64, true><<<PP / 256, 256>>>(x1, w1, b1, bnA, bnC, x2);
    stats_kernel<<<dim3(64, 32), 256>>>(x2, psum, psq);
    bn_finalize_kernel<<<1, 64>>>(psum, psq, g1, be1, bnA, bnC, 64);
    // 5) layer 3: 64 -> 128 (two 64-out halves, BN2+ReLU fused on input)
    conv64_kernel<64, true><<<PP / 256, 256>>>(x2, w2,           b2,      bnA, bnC, x3);
    conv64_kernel<64, true><<<PP / 256, 256>>>(x2, w2 + 64 * 64, b2 + 64, bnA, bnC,
                                               x3 + (size_t)64 * PP);
    stats_kernel<<<dim3(128, 32), 256>>>(x3, psum, psq);
    bn_finalize_kernel<<<1, 128>>>(psum, psq, g2, be2, bnA, bnC, 128);
    // 6) BN3 + ReLU + max over samples
    maxpool_kernel<<<(BB * NPOINTS * 128) / 256, 256>>>(x3, bnA, bnC, out_feat);
}

// round 15
// speedup vs baseline: 1.1327x; 1.0035x over previous
#include <cuda_runtime.h>
#include <math.h>
#include <stdint.h>

// Problem constants
#define BB      8
#define NN      8192
#define DD      16
#define NPOINTS 1024
#define NSAMP   32
#define PP      (BB * NPOINTS * NSAMP)   // 262144 positions
#define R2      0.04f
#define NEWXYZ_ELEMS (BB * NPOINTS * 3)

typedef unsigned long long ull;

// ---------------- packed f32x2 helpers (sm_103a) ----------------
__device__ __forceinline__ ull pk2(float lo, float hi) {
    ull r; asm("mov.b64 %0, {%1, %2};" : "=l"(r) : "f"(lo), "f"(hi)); return r;
}
__device__ __forceinline__ void upk2(float& lo, float& hi, ull v) {
    asm("mov.b64 {%0, %1}, %2;" : "=f"(lo), "=f"(hi) : "l"(v));
}
__device__ __forceinline__ ull add2(ull a, ull b) {
    ull r; asm("add.rn.f32x2 %0, %1, %2;" : "=l"(r) : "l"(a), "l"(b)); return r;
}
__device__ __forceinline__ ull mul2(ull a, ull b) {
    ull r; asm("mul.rn.f32x2 %0, %1, %2;" : "=l"(r) : "l"(a), "l"(b)); return r;
}
__device__ __forceinline__ ull fma2(ull a, ull b, ull c) {
    ull r; asm("fma.rn.f32x2 %0, %1, %2, %3;" : "=l"(r) : "l"(a), "l"(b), "l"(c)); return r;
}
// one LDS.128 -> two aligned u64 packed operands
__device__ __forceinline__ void lds_w2(ull& a, ull& b, const float* p) {
    unsigned addr = (unsigned)__cvta_generic_to_shared(p);
    asm("ld.shared.v2.b64 {%0, %1}, [%2];" : "=l"(a), "=l"(b) : "r"(addr));
}

__device__ __forceinline__ int mor3(int v) {            // spread 3 bits
    return (v & 1) | ((v & 2) << 2) | ((v & 4) << 4);
}

// ---------------- scratch (device globals: allocation-free) ----------------
__device__ float g_feat0[19 * PP];     // grouped features, channel-major [c][pos]
__device__ float g_x1[64 * PP];        // layer1 pre-BN
__device__ float g_x2[64 * PP];        // layer2 pre-BN
__device__ float g_x3[128 * PP];       // layer3 pre-BN
__device__ int   g_fps[BB * NPOINTS];
__device__ float g_psum[128 * 32];
__device__ float g_psq [128 * 32];
__device__ float g_bnA[128];
__device__ float g_bnC[128];

// ==========================================================================
// 1) Farthest point sampling — one block per batch, exact JAX semantics,
//    with EXACT warp-level spatial pruning:
//      * points Morton-binned once; warp w owns binned slots [512w, 512w+512)
//      * per-thread 16 points SORTED by original index (strict-> scan ==
//        min-orig-index tie-break, matching jnp.argmax)
//      * per iteration, warp skips its update iff
//          boxdist^2(centroid, warp bbox) * 0.999 >= warp max dist
//        which guarantees d(p,c) >= dist[p] for every owned point, so the
//        stored dists / warp max / warp argmax remain bitwise valid.
//    Atomic scatter makes the PARTITION nondeterministic, but max / min-index
//    reductions over the full point set are partition-independent, so the
//    selected index sequence (and all outputs) are bitwise deterministic.
// ==========================================================================
__global__ void __launch_bounds__(512, 1)
fps_kernel(const float* __restrict__ xyz, const int* __restrict__ init_far,
           int* __restrict__ fps_idx)
{
    extern __shared__ float sm[];
    float* xs = sm;                       // 8192 (binned after setup)
    float* ys = xs + 8192;
    float* zs = ys + 8192;
    int*   sidx = (int*)(zs + 8192);      // 1024 staged output indices
    unsigned* wbits = (unsigned*)(sidx + 1024); // [2][16] double-buffered
    unsigned* widx  = wbits + 32;               // [2][16]
    unsigned* cnt   = widx + 32;          // 512 cell counts
    unsigned* sptr  = cnt + 512;          // 512 scatter pointers
    unsigned* wsum  = sptr + 512;         // 16 warp partial sums
    unsigned short* posof = (unsigned short*)(wsum + 16);  // 8192: orig -> binpos
    unsigned short* oidx  = posof + 8192;                  // 8192: binpos -> orig

    const int b    = blockIdx.x;
    const int tid  = threadIdx.x;         // 0..511
    const int lane = tid & 31, wrp = tid >> 5;
    const float* base = xyz + (size_t)b * NN * 3;

    // ---- load xyz into SoA smem (orig order) ----
    for (int i = tid; i < NN * 3; i += 512) {
        float v = base[i];
        int p = i / 3, c = i - p * 3;
        if (c == 0) xs[p] = v; else if (c == 1) ys[p] = v; else zs[p] = v;
    }
    cnt[tid] = 0;
    __syncthreads();

    // ---- read 16 orig points to regs, histogram Morton cells ----
    float x[16], y[16], z[16];
    unsigned o[16];
#pragma unroll
    for (int j = 0; j < 16; j++) {
        int p = tid + j * 512;
        x[j] = xs[p]; y[j] = ys[p]; z[j] = zs[p]; o[j] = (unsigned)p;
        int cx = min(7, (int)(x[j] * 8.0f));
        int cy = min(7, (int)(y[j] * 8.0f));
        int cz = min(7, (int)(z[j] * 8.0f));
        atomicAdd(&cnt[mor3(cx) | (mor3(cy) << 1) | (mor3(cz) << 2)], 1u);
    }
    __syncthreads();

    // ---- exclusive scan of cnt[512] -> sptr ----
    {
        unsigned c0 = cnt[tid], ci = c0;
#pragma unroll
        for (int off = 1; off < 32; off <<= 1) {
            unsigned n = __shfl_up_sync(0xffffffffu, ci, off);
            if (lane >= off) ci += n;
        }
        if (lane == 31) wsum[wrp] = ci;
        __syncthreads();
        unsigned woff = 0;
        for (int w = 0; w < wrp; w++) woff += wsum[w];
        sptr[tid] = woff + ci - c0;
    }
    __syncthreads();

    // ---- scatter into binned order (overwrites xs/ys/zs; coords in regs) ----
#pragma unroll
    for (int j = 0; j < 16; j++) {
        int cx = min(7, (int)(x[j] * 8.0f));
        int cy = min(7, (int)(y[j] * 8.0f));
        int cz = min(7, (int)(z[j] * 8.0f));
        int cell = mor3(cx) | (mor3(cy) << 1) | (mor3(cz) << 2);
        unsigned pos = atomicAdd(&sptr[cell], 1u);
        xs[pos] = x[j]; ys[pos] = y[j]; zs[pos] = z[j];
        oidx[pos]  = (unsigned short)o[j];
        posof[o[j]] = (unsigned short)pos;
    }
    __syncthreads();

    // ---- re-read this warp's 512-slot region: thread takes lane + 32j ----
#pragma unroll
    for (int j = 0; j < 16; j++) {
        int p = wrp * 512 + lane + j * 32;
        x[j] = xs[p]; y[j] = ys[p]; z[j] = zs[p];
        o[j] = (unsigned)oidx[p];
    }

    // ---- sort 16 tuples by orig index ascending (static exchange network) ----
#pragma unroll
    for (int a = 0; a < 15; a++)
#pragma unroll
        for (int bq = a + 1; bq < 16; bq++)
            if (o[bq] < o[a]) {
                unsigned to = o[a]; o[a] = o[bq]; o[bq] = to;
                float t;
                t = x[a]; x[a] = x[bq]; x[bq] = t;
                t = y[a]; y[a] = y[bq]; y[bq] = t;
                t = z[a]; z[a] = z[bq]; z[bq] = t;
            }

    // ---- warp bbox over its 512 points (coords >= 0: bits monotone) ----
    float xl = x[0], xh = x[0], yl = y[0], yh = y[0], zl = z[0], zh = z[0];
#pragma unroll
    for (int j = 1; j < 16; j++) {
        xl = fminf(xl, x[j]); xh = fmaxf(xh, x[j]);
        yl = fminf(yl, y[j]); yh = fmaxf(yh, y[j]);
        zl = fminf(zl, z[j]); zh = fmaxf(zh, z[j]);
    }
    xl = __uint_as_float(__reduce_min_sync(0xffffffffu, __float_as_uint(xl)));
    xh = __uint_as_float(__reduce_max_sync(0xffffffffu, __float_as_uint(xh)));
    yl = __uint_as_float(__reduce_min_sync(0xffffffffu, __float_as_uint(yl)));
    yh = __uint_as_float(__reduce_max_sync(0xffffffffu, __float_as_uint(yh)));
    zl = __uint_as_float(__reduce_min_sync(0xffffffffu, __float_as_uint(zl)));
    zh = __uint_as_float(__reduce_max_sync(0xffffffffu, __float_as_uint(zh)));

    // ---- pack coordinate pairs (scan order j=0..15 == ascending orig) ----
    ull px2[8], py2[8], pz2[8];
    float dist[16];
#pragma unroll
    for (int k = 0; k < 8; k++) {
        px2[k] = pk2(x[2 * k], x[2 * k + 1]);
        py2[k] = pk2(y[2 * k], y[2 * k + 1]);
        pz2[k] = pk2(z[2 * k], z[2 * k + 1]);
        dist[2 * k] = 1e10f; dist[2 * k + 1] = 1e10f;
    }

    unsigned wm = __float_as_uint(1e10f);   // warp max dist (persistent)
    unsigned wi = 0;                        // its min orig index (persistent)
    int far = init_far[b];
    int par = 0;

    for (int it = 0; it < NPOINTS; ++it) {
        if (tid == 0) sidx[it] = far;       // record BEFORE update (scan semantics)
        const int binp = (int)posof[far];   // centroid position in binned arrays
        const float cx = xs[binp], cy = ys[binp], cz = zs[binp];

        // exact warp-level prune: skip iff boxdist^2*0.999 >= warp max dist
        float gx = fmaxf(fmaxf(xl - cx, cx - xh), 0.0f);
        float gy = fmaxf(fmaxf(yl - cy, cy - yh), 0.0f);
        float gz = fmaxf(fmaxf(zl - cz, cz - zh), 0.0f);
        float lb = (gx * gx + gy * gy + gz * gz) * 0.999f;

        if (lb < __uint_as_float(wm)) {     // ACTIVE: do the real update
            const ull ncx = pk2(-cx, -cx);
            const ull ncy = pk2(-cy, -cy);
            const ull ncz = pk2(-cz, -cz);
            float best = -1.0f; unsigned borig = 0;
#pragma unroll
            for (int k = 0; k < 8; k++) {
                ull dx = add2(px2[k], ncx);   // == fsub.rn per half
                ull dy = add2(py2[k], ncy);
                ull dz = add2(pz2[k], ncz);
                ull s  = add2(add2(mul2(dx, dx), mul2(dy, dy)), mul2(dz, dz));
                float d0, d1; upk2(d0, d1, s);
                float n0 = fminf(dist[2 * k], d0);     dist[2 * k] = n0;
                float n1 = fminf(dist[2 * k + 1], d1); dist[2 * k + 1] = n1;
                if (n0 > best) { best = n0; borig = o[2 * k]; }     // strict >
                if (n1 > best) { best = n1; borig = o[2 * k + 1]; } // == first max
            }
            unsigned bb = __float_as_uint(best);
            wm = __reduce_max_sync(0xffffffffu, bb);
            unsigned ci = (bb == wm) ? borig : 0xffffffffu;
            wi = __reduce_min_sync(0xffffffffu, ci);
        }
        if (lane == 0) { wbits[par * 16 + wrp] = wm; widx[par * 16 + wrp] = wi; }
        __syncthreads();
        // every warp redundantly reduces the 16 slots -> single barrier/iter
        unsigned b2 = (lane < 16) ? wbits[par * 16 + lane] : 0u;
        unsigned i2 = (lane < 16) ? widx [par * 16 + lane] : 0xffffffffu;
        unsigned m2 = __reduce_max_sync(0xffffffffu, b2);
        unsigned c2 = (b2 == m2) ? i2 : 0xffffffffu;
        far = (int)__reduce_min_sync(0xffffffffu, c2);
        par ^= 1;
    }
    __syncthreads();
    for (int i = tid; i < NPOINTS; i += 512) fps_idx[b * NPOINTS + i] = sidx[i];
}

// ==========================================================================
// 2) Ball query + grouping — one warp per (b, s). First 32 indices (ascending)
//    with sq <= r^2; pad with the first. Writes new_xyz to d_out and grouped
//    features [3 xyz-norm + 16 points] channel-major into g_feat0.
// ==========================================================================
__global__ void __launch_bounds__(256)
ball_group_kernel(const float* __restrict__ xyz, const float* __restrict__ pts,
                  const int* __restrict__ fps_idx,
                  float* __restrict__ newxyz_out, float* __restrict__ feat0)
{
    __shared__ int buf[8][NSAMP];
    const int gw = (blockIdx.x * blockDim.x + threadIdx.x) >> 5;
    const int lane = threadIdx.x & 31;
    const int wloc = (threadIdx.x >> 5);
    if (gw >= BB * NPOINTS) return;
    const int b = gw >> 10;

    const float* xb = xyz + (size_t)b * NN * 3;
    const int cidx = fps_idx[gw];
    const float cx = xb[cidx * 3], cy = xb[cidx * 3 + 1], cz = xb[cidx * 3 + 2];
    if (lane < 3) newxyz_out[gw * 3 + lane] = xb[cidx * 3 + lane];

    const float c2 = __fadd_rn(__fadd_rn(__fmul_rn(cx, cx), __fmul_rn(cy, cy)),
                               __fmul_rn(cz, cz));
    int cnt = 0;
    for (int chunk = 0; chunk < NN / 32 && cnt < NSAMP; ++chunk) {
        const int p = chunk * 32 + lane;
        const float x = xb[p * 3], y = xb[p * 3 + 1], z = xb[p * 3 + 2];
        const float dot = fmaf(z, cz, fmaf(y, cy, __fmul_rn(x, cx)));
        const float p2  = __fadd_rn(__fadd_rn(__fmul_rn(x, x), __fmul_rn(y, y)),
                                    __fmul_rn(z, z));
        const float sq  = __fadd_rn(__fadd_rn(__fmul_rn(-2.0f, dot), c2), p2);
        const bool pred = !(sq > R2);
        const unsigned m = __ballot_sync(0xffffffffu, pred);
        if (pred) {
            const int pos = cnt + __popc(m & ((1u << lane) - 1u));
            if (pos < NSAMP) buf[wloc][pos] = p;
        }
        cnt += __popc(m);
    }
    __syncwarp();
    if (cnt < NSAMP) {
        const int first = buf[wloc][0];   // cnt >= 1 always (center itself qualifies)
        if (lane >= cnt) buf[wloc][lane] = first;
    }
    __syncwarp();

    // gather: lane k handles sample k
    const int gi = buf[wloc][lane];
    const float* gp = xb + gi * 3;
    const size_t posn = (size_t)gw * NSAMP + lane;
    feat0[0 * (size_t)PP + posn] = __fsub_rn(gp[0], cx);
    feat0[1 * (size_t)PP + posn] = __fsub_rn(gp[1], cy);
    feat0[2 * (size_t)PP + posn] = __fsub_rn(gp[2], cz);
    const float* pr = pts + ((size_t)b * NN + gi) * DD;
#pragma unroll
    for (int c = 0; c < DD; c++)
        feat0[(size_t)(3 + c) * PP + posn] = pr[c];
}

// ==========================================================================
// 3) Pointwise conv (CIN -> 64), optional fused BN+ReLU on the input.
//    1 thread = 1 position; 32 PACKED f32x2 accumulators (pairs of output
//    channels). Weights read via ld.shared.v2.b64 (one LDS.128 broadcast).
// ==========================================================================
template <int CIN, bool HASBN>
__global__ void __launch_bounds__(256)
conv64_kernel(const float* __restrict__ in, const float* __restrict__ w,
              const float* __restrict__ bias,
              const float* __restrict__ bnA, const float* __restrict__ bnC,
              float* __restrict__ out)
{
    __shared__ __align__(16) float ws[CIN * 64];   // [c][o]
    __shared__ float sA[CIN], sC[CIN], sB[64];
    const int tid = threadIdx.x;
    for (int i = tid; i < CIN * 64; i += 256) {
        int o = i / CIN, c = i - o * CIN;
        ws[c * 64 + o] = w[i];
    }
    if (tid < 64) sB[tid] = bias[tid];
    if (HASBN) for (int i = tid; i < CIN; i += 256) { sA[i] = bnA[i]; sC[i] = bnC[i]; }
    __syncthreads();

    const int pos = blockIdx.x * 256 + tid;
    ull acc[32];
#pragma unroll
    for (int j = 0; j < 32; j++) acc[j] = pk2(sB[2 * j], sB[2 * j + 1]);

#pragma unroll 4
    for (int c = 0; c < CIN; c++) {
        float v = in[(size_t)c * PP + pos];
        if (HASBN) v = fmaxf(fmaf(v, sA[c], sC[c]), 0.0f);
        const ull vv = pk2(v, v);
        const float* wr = ws + c * 64;
#pragma unroll
        for (int j = 0; j < 16; j++) {
            ull w01, w23;
            lds_w2(w01, w23, wr + 4 * j);          // LDS.128 broadcast
            acc[2 * j]     = fma2(w01, vv, acc[2 * j]);
            acc[2 * j + 1] = fma2(w23, vv, acc[2 * j + 1]);
        }
    }
#pragma unroll
    for (int j = 0; j < 32; j++) {
        float a0, a1; upk2(a0, a1, acc[j]);
        out[(size_t)(2 * j)     * PP + pos] = a0;
        out[(size_t)(2 * j + 1) * PP + pos] = a1;
    }
}

// ==========================================================================
// 4) Deterministic per-channel stats (sum, sumsq): grid (C, 32 slices).
//    float4 loads for DRAM efficiency.
// ==========================================================================
__global__ void __launch_bounds__(256)
stats_kernel(const float* __restrict__ x, float* __restrict__ psum,
             float* __restrict__ psq)
{
    const int c = blockIdx.x, sl = blockIdx.y;
    const float4* p = reinterpret_cast<const float4*>(
        x + (size_t)c * PP + (size_t)sl * 8192);
    float s = 0.f, q = 0.f;
    for (int i = threadIdx.x; i < 2048; i += 256) {
        float4 v = p[i];
        s += v.x; q += v.x * v.x;
        s += v.y; q += v.y * v.y;
        s += v.z; q += v.z * v.z;
        s += v.w; q += v.w * v.w;
    }
    __shared__ float rs[256], rq[256];
    rs[threadIdx.x] = s; rq[threadIdx.x] = q;
    __syncthreads();
    for (int st = 128; st > 0; st >>= 1) {
        if (threadIdx.x < st) {
            rs[threadIdx.x] += rs[threadIdx.x + st];
            rq[threadIdx.x] += rq[threadIdx.x + st];
        }
        __syncthreads();
    }
    if (threadIdx.x == 0) { psum[c * 32 + sl] = rs[0]; psq[c * 32 + sl] = rq[0]; }
}

__global__ void bn_finalize_kernel(const float* __restrict__ psum,
                                   const float* __restrict__ psq,
                                   const float* __restrict__ g,
                                   const float* __restrict__ be,
                                   float* __restrict__ A, float* __restrict__ C,
                                   int nC)
{
    const int c = blockIdx.x * blockDim.x + threadIdx.x;
    if (c >= nC) return;
    double s = 0.0, q = 0.0;
    for (int i = 0; i < 32; i++) { s += (double)psum[c * 32 + i]; q += (double)psq[c * 32 + i]; }
    const double mean = s / (double)PP;
    const double var  = q / (double)PP - mean * mean;
    const double inv  = 1.0 / sqrt(var + 1e-5);
    const double a    = (double)g[c] * inv;
    A[c] = (float)a;
    C[c] = (float)((double)be[c] - mean * a);
}

// ==========================================================================
// 5) BN + ReLU + max over the 32 samples; writes (B, S, 128) part of d_out.
// ==========================================================================
__global__ void __launch_bounds__(256)
maxpool_kernel(const float* __restrict__ x, const float* __restrict__ A,
               const float* __restrict__ C, float* __restrict__ out)
{
    const int idx = blockIdx.x * 256 + threadIdx.x;  // < 8*1024*128
    const int o = idx & 127, bs = idx >> 7;
    const float4* p = reinterpret_cast<const float4*>(x + (size_t)o * PP + (size_t)bs * NSAMP);
    const float a = A[o], cc = C[o];
    float m = -1e30f;
#pragma unroll
    for (int k = 0; k < 8; k++) {
        float4 v = p[k];
        m = fmaxf(m, fmaf(v.x, a, cc));
        m = fmaxf(m, fmaf(v.y, a, cc));
        m = fmaxf(m, fmaf(v.z, a, cc));
        m = fmaxf(m, fmaf(v.w, a, cc));
    }
    out[idx] = fmaxf(m, 0.0f);   // relu commutes with max
}

// ==========================================================================
// launch
// ==========================================================================
extern "C" void kernel_launch(void* const* d_in, const int* in_sizes, int n_in,
                              void* d_out, int out_size)
{
    const float* xyz      = (const float*)d_in[0];
    const float* pts      = (const float*)d_in[1];
    const int*   init_far = (const int*)  d_in[2];
    const float* w0 = (const float*)d_in[3],  *b0 = (const float*)d_in[4];
    const float* g0 = (const float*)d_in[5],  *be0 = (const float*)d_in[6];
    const float* w1 = (const float*)d_in[7],  *b1 = (const float*)d_in[8];
    const float* g1 = (const float*)d_in[9],  *be1 = (const float*)d_in[10];
    const float* w2 = (const float*)d_in[11], *b2 = (const float*)d_in[12];
    const float* g2 = (const float*)d_in[13], *be2 = (const float*)d_in[14];

    float* out = (float*)d_out;
    float* out_newxyz = out;                  // (B, 1024, 3)
    float* out_feat   = out + NEWXYZ_ELEMS;   // (B, 1024, 128)

    float *feat0, *x1, *x2, *x3, *psum, *psq, *bnA, *bnC;
    int* fpsIdx;
    cudaGetSymbolAddress((void**)&feat0,  g_feat0);
    cudaGetSymbolAddress((void**)&x1,     g_x1);
    cudaGetSymbolAddress((void**)&x2,     g_x2);
    cudaGetSymbolAddress((void**)&x3,     g_x3);
    cudaGetSymbolAddress((void**)&psum,   g_psum);
    cudaGetSymbolAddress((void**)&psq,    g_psq);
    cudaGetSymbolAddress((void**)&bnA,    g_bnA);
    cudaGetSymbolAddress((void**)&bnC,    g_bnC);
    cudaGetSymbolAddress((void**)&fpsIdx, g_fps);

    // smem: xs/ys/zs(3*8192) + sidx(1024) + slots(64) + cnt(512)+sptr(512)+wsum(16)
    //       floats, + 2 * 8192 u16
    const int fps_smem = (3 * 8192 + 1024 + 64 + 512 + 512 + 16) * 4
                       + 2 * 8192 * 2 + 256;
    cudaFuncSetAttribute(fps_kernel, cudaFuncAttributeMaxDynamicSharedMemorySize, fps_smem);

    // 1) FPS (spatially-pruned, exact)
    fps_kernel<<<BB, 512, fps_smem>>>(xyz, init_far, fpsIdx);
    // 2) ball query + grouping (+ writes new_xyz)
    ball_group_kernel<<<(BB * NPOINTS) / 8, 256>>>(xyz, pts, fpsIdx, out_newxyz, feat0);
    // 3) layer 1: 19 -> 64
    conv64_kernel<19, false><<<PP / 256, 256>>>(feat0, w0, b0, nullptr, nullptr, x1);
    stats_kernel<<<dim3(64, 32), 256>>>(x1, psum, psq);
    bn_finalize_kernel<<<1, 64>>>(psum, psq, g0, be0, bnA, bnC, 64);
    // 4) layer 2: 64 -> 64 (BN1+ReLU fused on input)
    conv64_kernel<64, true><<<PP / 256, 256>>>(x1, w1, b1, bnA, bnC, x2);
    stats_kernel<<<dim3(64, 32), 256>>>(x2, psum, psq);
    bn_finalize_kernel<<<1, 64>>>(psum, psq, g1, be1, bnA, bnC, 64);
    // 5) layer 3: 64 -> 128 (two 64-out halves, BN2+ReLU fused on input)
    conv64_kernel<64, true><<<PP / 256, 256>>>(x2, w2,           b2,      bnA, bnC, x3);
    conv64_kernel<64, true><<<PP / 256, 256>>>(x2, w2 + 64 * 64, b2 + 64, bnA, bnC,
                                               x3 + (size_t)64 * PP);
    stats_kernel<<<dim3(128, 32), 256>>>(x3, psum, psq);
    bn_finalize_kernel<<<1, 128>>>(psum, psq, g2, be2, bnA, bnC, 128);
    // 6) BN3 + ReLU + max over samples
    maxpool_kernel<<<(BB * NPOINTS * 128) / 256, 256>>>(x3, bnA, bnC, out_feat);
}